// round 1
// baseline (speedup 1.0000x reference)
#include <cuda_runtime.h>
#include <cuda_bf16.h>
#include <math.h>

#define BB 8
#define PP 2048
#define CC 21
#define CENTER_VAR 0.1f
#define SIZE_VAR 0.2f
#define GEPS 1e-8f

// Scratch (device globals; zero-initialized at load, init kernel re-zeros every launch)
__device__ float4 g_boxA[BB][PP];   // decoded inferred-positive boxes, compacted
__device__ float4 g_boxT[BB][PP];   // decoded target-positive boxes, compacted
__device__ int    g_cntA[BB];
__device__ int    g_cntT[BB];
__device__ float  g_S[BB];
__device__ int    g_i64_probe;      // nonzero if any odd word nonzero -> int32
__device__ int    g_is64;           // final flag: 1 if target_confidence is int64

// ---------------------------------------------------------------------------
// Kernel 0: reset accumulators + detect int32 vs int64 target_confidence.
// Values are in {0,1}; if int64 (little-endian), odd 32-bit words over the
// first 256 words are all zero. 256 words is in-bounds for both framings.
// ---------------------------------------------------------------------------
__global__ void init_kernel(const int* __restrict__ tc_words) {
    int t = threadIdx.x;
    if (t == 0) g_i64_probe = 0;
    __syncthreads();
    if (t < BB) { g_cntA[t] = 0; g_cntT[t] = 0; g_S[t] = 0.f; }
    if (t < 128) {
        if (tc_words[2 * t + 1] != 0) atomicOr(&g_i64_probe, 1);
    }
    __syncthreads();
    if (t == 0) g_is64 = (g_i64_probe == 0) ? 1 : 0;
}

// ---------------------------------------------------------------------------
// Kernel 1: per (b,p) classify (softmax max/argmax), decode boxes, compact.
// ---------------------------------------------------------------------------
__global__ void classify_decode(const float* __restrict__ conf,
                                const float* __restrict__ loc,
                                const int*   __restrict__ tc,
                                const float* __restrict__ tloc,
                                const float* __restrict__ priors) {
    int idx = blockIdx.x * blockDim.x + threadIdx.x;
    if (idx >= BB * PP) return;
    int b = idx / PP;
    int p = idx - b * PP;

    int tv = g_is64 ? tc[2 * idx] : tc[idx];   // low word suffices for 0/1
    if (tv <= 0) return;                        // not pos_target -> contributes nothing

    // priors (center form)
    float pcx = priors[p * 4 + 0];
    float pcy = priors[p * 4 + 1];
    float pw  = priors[p * 4 + 2];
    float ph  = priors[p * 4 + 3];

    // decode target box -> compacted T list
    {
        const float* l = tloc + (size_t)idx * 4;
        float cx = pcx + l[0] * CENTER_VAR * pw;
        float cy = pcy + l[1] * CENTER_VAR * ph;
        float w  = pw * expf(l[2] * SIZE_VAR);
        float h  = ph * expf(l[3] * SIZE_VAR);
        float x0 = cx - 0.5f * w;
        float y0 = cy - 0.5f * h;
        int s = atomicAdd(&g_cntT[b], 1);
        g_boxT[b][s] = make_float4(x0, y0, x0 + w, y0 + h);
    }

    // softmax max-prob + argmax (only needed when pos_target)
    const float* cf = conf + (size_t)idx * CC;
    float m = cf[0];
    int mi = 0;
    #pragma unroll
    for (int c = 1; c < CC; c++) {
        float v = cf[c];
        if (v > m) { m = v; mi = c; }
    }
    float se = 0.f;
    #pragma unroll
    for (int c = 0; c < CC; c++) se += expf(cf[c] - m);
    float maxp = 1.f / se;

    if (maxp > 0.5f && mi > 0) {
        const float* l = loc + (size_t)idx * 4;
        float cx = pcx + l[0] * CENTER_VAR * pw;
        float cy = pcy + l[1] * CENTER_VAR * ph;
        float w  = pw * expf(l[2] * SIZE_VAR);
        float h  = ph * expf(l[3] * SIZE_VAR);
        float x0 = cx - 0.5f * w;
        float y0 = cy - 0.5f * h;
        int s = atomicAdd(&g_cntA[b], 1);
        g_boxA[b][s] = make_float4(x0, y0, x0 + w, y0 + h);
    }
}

// ---------------------------------------------------------------------------
// Kernel 2: masked pairwise GIoU sum over compacted lists (smem-tiled).
// grid = (8, BB), block = 256. Sum is order-independent.
// ---------------------------------------------------------------------------
#define TTILE 256
__global__ void pair_kernel() {
    int b = blockIdx.y;
    int nA = g_cntA[b];
    int nT = g_cntT[b];
    if (nA == 0 || nT == 0) return;

    __shared__ float4 sT[TTILE];
    float acc = 0.f;

    for (int t0 = 0; t0 < nT; t0 += TTILE) {
        int cnt = min(TTILE, nT - t0);
        __syncthreads();
        for (int i = threadIdx.x; i < cnt; i += blockDim.x)
            sT[i] = g_boxT[b][t0 + i];
        __syncthreads();

        for (int a = blockIdx.x * blockDim.x + threadIdx.x; a < nA;
             a += gridDim.x * blockDim.x) {
            float4 A = g_boxA[b][a];
            float areaA = (A.z - A.x) * (A.w - A.y);
            for (int j = 0; j < cnt; j++) {
                float4 T = sT[j];
                float ix = fminf(A.z, T.z) - fmaxf(A.x, T.x);
                float iy = fminf(A.w, T.w) - fmaxf(A.y, T.y);
                float inter = fmaxf(ix, 0.f) * fmaxf(iy, 0.f);
                float areaT = (T.z - T.x) * (T.w - T.y);
                float uni = areaA + areaT - inter;
                float iou = inter / fmaxf(uni, GEPS);
                float ex = fmaxf(A.z, T.z) - fminf(A.x, T.x);
                float ey = fmaxf(A.w, T.w) - fminf(A.y, T.y);
                float enc = ex * ey;
                acc += iou - (enc - uni) / fmaxf(enc, GEPS);
            }
        }
    }

    // warp reduce then one atomic per warp
    #pragma unroll
    for (int o = 16; o > 0; o >>= 1)
        acc += __shfl_down_sync(0xFFFFFFFFu, acc, o);
    if ((threadIdx.x & 31) == 0) atomicAdd(&g_S[b], acc);
}

// ---------------------------------------------------------------------------
// Kernel 3: finalize scalar.
// ---------------------------------------------------------------------------
__global__ void finalize_kernel(float* __restrict__ out) {
    if (threadIdx.x == 0) {
        float tsum = 0.f, ntsum = 0.f;
        #pragma unroll
        for (int b = 0; b < BB; b++) {
            float nt = (float)g_cntT[b];
            float na = (float)g_cntA[b];
            bool bt = nt > 0.f, ba = na > 0.f;
            float term;
            if (bt && ba)      term = nt - g_S[b] / fmaxf(nt, 1.f);
            else if (bt != ba) term = 1.f;
            else               term = 0.f;
            tsum += term;
            ntsum += nt;
        }
        out[0] = tsum / fmaxf(ntsum, 1.f);
    }
}

// ---------------------------------------------------------------------------
// Inputs (metadata order): confidence f32 [8,2048,21], locations f32 [8,2048,4],
// target_confidence int [8,2048], target_locations f32 [8,2048,4], priors f32 [2048,4]
// Output: f32 scalar.
// ---------------------------------------------------------------------------
extern "C" void kernel_launch(void* const* d_in, const int* in_sizes, int n_in,
                              void* d_out, int out_size) {
    const float* conf   = (const float*)d_in[0];
    const float* loc    = (const float*)d_in[1];
    const int*   tc     = (const int*)d_in[2];
    const float* tloc   = (const float*)d_in[3];
    const float* priors = (const float*)d_in[4];
    float* out = (float*)d_out;

    init_kernel<<<1, 256>>>(tc);
    classify_decode<<<(BB * PP + 255) / 256, 256>>>(conf, loc, tc, tloc, priors);
    dim3 pg(8, BB);
    pair_kernel<<<pg, 256>>>();
    finalize_kernel<<<1, 32>>>(out);
}